// round 15
// baseline (speedup 1.0000x reference)
#include <cuda_runtime.h>
#include <cuda_fp16.h>
#include <cstdint>

#define N_ROWS 8192
#define S_ROWS 4096
#define C_DIM  256

// ---------------- scratch (static device arrays; no runtime allocation) ----
__device__ __align__(16) __half g_Sh[N_ROWS * C_DIM];
__device__ __align__(16) __half g_Fh[N_ROWS * C_DIM];
__device__ __align__(16) __half g_Vh[S_ROWS * C_DIM];
__device__ __align__(16) __half g_Kh[S_ROWS * C_DIM];
__device__ __align__(16) __half g_Vth[C_DIM * S_ROWS];
__device__ __align__(16) __half g_Ph[(size_t)2 * N_ROWS * S_ROWS];
// split-K partials for merged recall GEMM: [2 splits][16384, 256] fp32
__device__ __align__(16) float g_part[(size_t)2 * 2 * N_ROWS * C_DIM];

// ---------------- fast exp on FMA pipe ------------------------------------
__device__ __forceinline__ float fexp(float x) {
    x = fmaxf(x, -80.0f);
    float z = fmaf(x, 1.4426950408889634f, 12582912.0f);
    float n = z - 12582912.0f;
    float r = fmaf(n, -0.69314718055994531f, x);
    float p = 1.3888889e-3f;
    p = fmaf(p, r, 8.3333333e-3f);
    p = fmaf(p, r, 4.1666667e-2f);
    p = fmaf(p, r, 1.6666667e-1f);
    p = fmaf(p, r, 0.5f);
    p = fmaf(p, r, 1.0f);
    p = fmaf(p, r, 1.0f);
    int e = (int)n;
    return p * __int_as_float((e + 127) << 23);
}

// ---------------- row normalize -> fp16 -----------------------------------
__device__ __forceinline__ void norm_row(const float* __restrict__ x,
                                         __half* __restrict__ h,
                                         int row, int t) {
    __shared__ float warpred[8];
    __shared__ float rn_s;
    float v = x[(size_t)row * C_DIM + t];
    float s = v * v;
    #pragma unroll
    for (int o = 16; o > 0; o >>= 1) s += __shfl_xor_sync(0xffffffffu, s, o);
    if ((t & 31) == 0) warpred[t >> 5] = s;
    __syncthreads();
    if (t == 0) {
        float tot = 0.f;
        #pragma unroll
        for (int i = 0; i < 8; i++) tot += warpred[i];
        rn_s = rsqrtf(tot);
    }
    __syncthreads();
    h[(size_t)row * C_DIM + t] = __float2half_rn(v * rn_s);
}

// merged embedding normalize: rows [0,8192) speech, [8192,16384) face
__global__ __launch_bounds__(256) void norm_emb_k(const float* __restrict__ speech,
                                                  const float* __restrict__ face,
                                                  __half* __restrict__ Sh,
                                                  __half* __restrict__ Fh) {
    const int b = blockIdx.x;
    if (b < N_ROWS) norm_row(speech, Sh, b, threadIdx.x);
    else            norm_row(face, Fh, b - N_ROWS, threadIdx.x);
}

// merged memory normalize: rows [0,4096) svm, [4096,8192) fkm
__global__ __launch_bounds__(256) void norm_mem_k(const float* __restrict__ svm,
                                                  const float* __restrict__ fkm,
                                                  __half* __restrict__ Vh,
                                                  __half* __restrict__ Kh) {
    const int b = blockIdx.x;
    if (b < S_ROWS) norm_row(svm, Vh, b, threadIdx.x);
    else            norm_row(fkm, Kh, b - S_ROWS, threadIdx.x);
}

// ---------------- transpose raw svm [4096,256] -> [256,4096] fp16 ---------
__global__ void transpose_half_k(const float* __restrict__ V,
                                 __half* __restrict__ T) {
    __shared__ float ts[32][33];
    const int tx = threadIdx.x, ty = threadIdx.y;          // 32 x 8
    const int n0 = blockIdx.x * 32, k0 = blockIdx.y * 32;
    #pragma unroll
    for (int j = 0; j < 4; j++)
        ts[ty + 8 * j][tx] = V[(size_t)(k0 + ty + 8 * j) * C_DIM + n0 + tx];
    __syncthreads();
    #pragma unroll
    for (int j = 0; j < 4; j++) {
        int n = n0 + ty + 8 * j;
        int k = k0 + tx;
        T[(size_t)n * S_ROWS + k] = __float2half_rn(ts[tx][ty + 8 * j]);
    }
}

// ---------------- in-place log-softmax + P=exp(logsm) fp16 ----------------
__global__ __launch_bounds__(256) void softmax_rows_k(float* __restrict__ base,
                                                      __half* __restrict__ P) {
    __shared__ float warpred[8];
    __shared__ float bc;
    const size_t rbase = (size_t)blockIdx.x * 4096;
    float* p = base + rbase;
    const int t = threadIdx.x;
    float x[16];
    #pragma unroll
    for (int i = 0; i < 4; i++) {
        float4 v = *(const float4*)&p[i * 1024 + t * 4];
        x[i * 4 + 0] = v.x; x[i * 4 + 1] = v.y; x[i * 4 + 2] = v.z; x[i * 4 + 3] = v.w;
    }
    float mx = x[0];
    #pragma unroll
    for (int i = 1; i < 16; i++) mx = fmaxf(mx, x[i]);
    #pragma unroll
    for (int o = 16; o > 0; o >>= 1) mx = fmaxf(mx, __shfl_xor_sync(0xffffffffu, mx, o));
    if ((t & 31) == 0) warpred[t >> 5] = mx;
    __syncthreads();
    if (t == 0) {
        float m = warpred[0];
        #pragma unroll
        for (int i = 1; i < 8; i++) m = fmaxf(m, warpred[i]);
        bc = m;
    }
    __syncthreads();
    mx = bc;
    __syncthreads();
    float s = 0.f;
    #pragma unroll
    for (int i = 0; i < 16; i++) s += fexp(x[i] - mx);
    #pragma unroll
    for (int o = 16; o > 0; o >>= 1) s += __shfl_xor_sync(0xffffffffu, s, o);
    if ((t & 31) == 0) warpred[t >> 5] = s;
    __syncthreads();
    if (t == 0) {
        float tot = 0.f;
        #pragma unroll
        for (int i = 0; i < 8; i++) tot += warpred[i];
        bc = mx + logf(tot);
    }
    __syncthreads();
    const float lse = bc;
    #pragma unroll
    for (int i = 0; i < 4; i++) {
        float l0 = x[i * 4 + 0] - lse, l1 = x[i * 4 + 1] - lse;
        float l2 = x[i * 4 + 2] - lse, l3 = x[i * 4 + 3] - lse;
        *(float4*)&p[i * 1024 + t * 4] = make_float4(l0, l1, l2, l3);
        __half2 a, b;
        a.x = __float2half_rn(fexp(l0)); a.y = __float2half_rn(fexp(l1));
        b.x = __float2half_rn(fexp(l2)); b.y = __float2half_rn(fexp(l3));
        *(__half2*)&P[rbase + i * 1024 + t * 4] = a;
        *(__half2*)&P[rbase + i * 1024 + t * 4 + 2] = b;
    }
}

// =================== HMMA fp16 single-pass GEMM ============================
// C[M,N] += over k-range: A * B^T, fp32 accumulate.
// A:[M,K] fp16 row-major, B:[N,K] fp16 row-major.
// CTA tile 128x128, BK=32, 8 warps (warp tile 64x32), 4-stage cp.async
// pipeline (prefetch distance 3 chunks hides DRAM/L2 latency).
// smem rows padded to 80B -> conflict-free ldmatrix. The stage barrier sits
// after ALL smem reads of the chunk but BEFORE the final 16 register-only
// MMAs, keeping the tensor queue fed across chunk boundaries.

#define ROWB 80             // bytes per smem row (32 fp16 data + 16B pad)
#define TILEB (128 * ROWB)  // 10240 B per operand tile
#define STAGEB (2 * TILEB)  // A,B = 20480 B
#define NSTAGE 4
#define GEMM_SMEM (NSTAGE * STAGEB)  // 81920

__device__ __forceinline__ void cp16(uint32_t d, const void* g) {
    asm volatile("cp.async.cg.shared.global [%0], [%1], 16;" :: "r"(d), "l"(g) : "memory");
}
__device__ __forceinline__ void ldsm_x4(uint32_t* r, uint32_t a) {
    asm volatile("ldmatrix.sync.aligned.m8n8.x4.shared.b16 {%0,%1,%2,%3}, [%4];"
                 : "=r"(r[0]), "=r"(r[1]), "=r"(r[2]), "=r"(r[3]) : "r"(a));
}
__device__ __forceinline__ void mma_fp16(float* d, const uint32_t* a, const uint32_t* b) {
    asm volatile(
        "mma.sync.aligned.m16n8k16.row.col.f32.f16.f16.f32 "
        "{%0,%1,%2,%3},{%4,%5,%6,%7},{%8,%9},{%0,%1,%2,%3};"
        : "+f"(d[0]), "+f"(d[1]), "+f"(d[2]), "+f"(d[3])
        : "r"(a[0]), "r"(a[1]), "r"(a[2]), "r"(a[3]), "r"(b[0]), "r"(b[1]));
}

__device__ __forceinline__ void gemm1_body(
    const __half* __restrict__ A, const __half* __restrict__ B,
    float* __restrict__ C, int K, int ldc, int ch0, int nch, int bm, int bn) {
    extern __shared__ char smem[];
    uint32_t sb;
    asm("{ .reg .u64 t; cvta.to.shared.u64 t, %1; cvt.u32.u64 %0, t; }" : "=r"(sb) : "l"(smem));
    const int tid = threadIdx.x;
    const int wid = tid >> 5, lane = tid & 31;
    const int wm = (wid >> 2) * 64;   // warp row base within CTA tile
    const int wn = (wid & 3) * 32;    // warp col base

    const __half* gA = A + (size_t)bm * 128 * K;
    const __half* gB = B + (size_t)bn * 128 * K;

    // per-thread cp.async assignment: q in [0,512): row=q>>2, 16B-chunk=q&3
    const int r0 = tid >> 2, c0 = (tid & 3);
    const int r1 = (tid + 256) >> 2, c1 = ((tid + 256) & 3);

    // ldmatrix per-lane offsets
    const uint32_t aoff = (uint32_t)(((lane & 7) + ((lane >> 3) & 1) * 8) * ROWB
                                     + (lane >> 4) * 16);
    const uint32_t boff4 = (uint32_t)(((lane >> 4) * 8 + (lane & 7)) * ROWB
                                      + ((lane >> 3) & 1) * 16);

    float acc[4][4][4];
    #pragma unroll
    for (int mi = 0; mi < 4; mi++)
        #pragma unroll
        for (int ni = 0; ni < 4; ni++)
            #pragma unroll
            for (int e = 0; e < 4; e++) acc[mi][ni][e] = 0.f;

    // ---- stage loader ----
    #define LOAD_STAGE(s, k0)                                                   \
    {                                                                           \
        uint32_t base = sb + (uint32_t)(s) * STAGEB;                            \
        size_t ga = (size_t)r0 * K + (k0) + c0 * 8;                             \
        uint32_t da = base + (uint32_t)(r0 * ROWB + c0 * 16);                   \
        cp16(da,         gA + ga);                                              \
        cp16(da + TILEB, gB + ga);                                              \
        size_t gb = (size_t)r1 * K + (k0) + c1 * 8;                             \
        uint32_t db = base + (uint32_t)(r1 * ROWB + c1 * 16);                   \
        cp16(db,         gA + gb);                                              \
        cp16(db + TILEB, gB + gb);                                              \
        asm volatile("cp.async.commit_group;" ::: "memory");                    \
    }

    // preload NSTAGE-1 stages
    LOAD_STAGE(0, ch0 * 32)
    if (nch > 1) LOAD_STAGE(1, (ch0 + 1) * 32)
    if (nch > 2) LOAD_STAGE(2, (ch0 + 2) * 32)

    for (int ch = 0; ch < nch; ch++) {
        // exact wait: stage ch data is committed in group #ch; allow
        // min(remaining, NSTAGE-2) younger groups to stay in flight.
        const int rem = nch - 1 - ch;
        if (rem >= 2)      { asm volatile("cp.async.wait_group 2;" ::: "memory"); }
        else if (rem == 1) { asm volatile("cp.async.wait_group 1;" ::: "memory"); }
        else               { asm volatile("cp.async.wait_group 0;" ::: "memory"); }
        __syncthreads();

        uint32_t stg = sb + (uint32_t)(ch & (NSTAGE - 1)) * STAGEB;
        uint32_t sA = stg;
        uint32_t sB = stg + TILEB;
        const bool prefetch = (ch + NSTAGE - 1 < nch);

        uint32_t af[4][4], bf[2][4];

        // ================= ks = 0 (ko = 0) =================
        #pragma unroll
        for (int g = 0; g < 2; g++)
            ldsm_x4(bf[g], sB + (wn + g * 16) * ROWB + boff4);
        #pragma unroll
        for (int mi = 0; mi < 4; mi++)
            ldsm_x4(af[mi], sA + (wm + mi * 16) * ROWB + aoff);
        #pragma unroll
        for (int mi = 0; mi < 4; mi++)
            #pragma unroll
            for (int ni = 0; ni < 4; ni++)
                mma_fp16(acc[mi][ni], af[mi], &bf[ni >> 1][(ni & 1) * 2]);

        // ================= ks = 1 (ko = 32) =================
        #pragma unroll
        for (int g = 0; g < 2; g++)
            ldsm_x4(bf[g], sB + (wn + g * 16) * ROWB + 32 + boff4);
        #pragma unroll
        for (int mi = 0; mi < 4; mi++)
            ldsm_x4(af[mi], sA + (wm + mi * 16) * ROWB + 32 + aoff);  // last smem reads

        if (prefetch) {
            __syncthreads();                 // all smem reads of chunk done
            LOAD_STAGE((ch + NSTAGE - 1) & (NSTAGE - 1), (ch0 + ch + NSTAGE - 1) * 32)
        }

        // register-only MMAs cover the barrier/prefetch window
        #pragma unroll
        for (int mi = 0; mi < 4; mi++)
            #pragma unroll
            for (int ni = 0; ni < 4; ni++)
                mma_fp16(acc[mi][ni], af[mi], &bf[ni >> 1][(ni & 1) * 2]);

        if (!prefetch && ch + 1 < nch) __syncthreads();  // protect stage reuse
    }

    // ---- epilogue: fragment layout -> global fp32 ----
    const int rr = lane >> 2;
    const int cc = (lane & 3) * 2;
    #pragma unroll
    for (int mi = 0; mi < 4; mi++) {
        int grow = bm * 128 + wm + mi * 16 + rr;
        #pragma unroll
        for (int ni = 0; ni < 4; ni++) {
            int gcol = bn * 128 + wn + ni * 8 + cc;
            *(float2*)&C[(size_t)grow * ldc + gcol] =
                make_float2(acc[mi][ni][0], acc[mi][ni][1]);
            *(float2*)&C[(size_t)(grow + 8) * ldc + gcol] =
                make_float2(acc[mi][ni][2], acc[mi][ni][3]);
        }
    }
    #undef LOAD_STAGE
}

// ---- merged logits GEMM: z=0 -> speech/svm, z=1 -> face/fkm --------------
__global__ __launch_bounds__(256, 2) void gemm_logits_k(
    const __half* __restrict__ Sh, const __half* __restrict__ Vh,
    const __half* __restrict__ Fh, const __half* __restrict__ Kh,
    float* __restrict__ C) {
    const int z = blockIdx.z;
    const __half* A = z ? Fh : Sh;
    const __half* B = z ? Kh : Vh;
    float* Cz = C + (size_t)z * N_ROWS * S_ROWS;
    gemm1_body(A, B, Cz, C_DIM, S_ROWS, 0, C_DIM / 32, blockIdx.y, blockIdx.x);
}

// ---- merged recall GEMM with split-K=2: M=16384, partials to g_part ------
__global__ __launch_bounds__(256, 2) void gemm_recall_k(
    const __half* __restrict__ P, const __half* __restrict__ Vt,
    float* __restrict__ part) {
    const int z = blockIdx.z;                       // K half
    float* Cz = part + (size_t)z * 2 * N_ROWS * C_DIM;
    gemm1_body(P, Vt, Cz, S_ROWS, C_DIM, z * 64, 64, blockIdx.y, blockIdx.x);
}

// ---- reduce split-K partials and scatter to the two recall outputs -------
__global__ __launch_bounds__(256) void reduce_recall_k(const float* __restrict__ part,
                                                       float* __restrict__ outS,
                                                       float* __restrict__ outF) {
    const size_t i = ((size_t)blockIdx.x * 256 + threadIdx.x) * 4;  // over 16384*256 floats
    float4 a = *(const float4*)&part[i];
    float4 b = *(const float4*)&part[i + (size_t)2 * N_ROWS * C_DIM];
    a.x += b.x; a.y += b.y; a.z += b.z; a.w += b.w;
    const size_t half = (size_t)N_ROWS * C_DIM;
    if (i < half) *(float4*)&outS[i] = a;
    else          *(float4*)&outF[i - half] = a;
}

// ---------------- launch ---------------------------------------------------
extern "C" void kernel_launch(void* const* d_in, const int* in_sizes, int n_in,
                              void* d_out, int out_size) {
    const float* face   = (const float*)d_in[0];
    const float* speech = (const float*)d_in[1];
    const float* svm    = (const float*)d_in[2];
    const float* fkm    = (const float*)d_in[3];
    float* out = (float*)d_out;

    __half *Sh, *Fh, *Vh, *Kh, *Vth, *Ph;
    float* Part;
    cudaGetSymbolAddress((void**)&Sh, g_Sh);
    cudaGetSymbolAddress((void**)&Fh, g_Fh);
    cudaGetSymbolAddress((void**)&Vh, g_Vh);
    cudaGetSymbolAddress((void**)&Kh, g_Kh);
    cudaGetSymbolAddress((void**)&Vth, g_Vth);
    cudaGetSymbolAddress((void**)&Ph, g_Ph);
    cudaGetSymbolAddress((void**)&Part, g_part);

    const size_t o_se  = 0;
    const size_t o_ser = 2097152;
    const size_t o_fe  = 4194304;
    const size_t o_fer = 6291456;
    const size_t o_sal = 8388608;

    cudaMemcpyAsync(out + o_se, speech, (size_t)N_ROWS * C_DIM * sizeof(float),
                    cudaMemcpyDeviceToDevice, 0);
    cudaMemcpyAsync(out + o_fe, face, (size_t)N_ROWS * C_DIM * sizeof(float),
                    cudaMemcpyDeviceToDevice, 0);

    cudaFuncSetAttribute(gemm_logits_k, cudaFuncAttributeMaxDynamicSharedMemorySize, GEMM_SMEM);
    cudaFuncSetAttribute(gemm_recall_k, cudaFuncAttributeMaxDynamicSharedMemorySize, GEMM_SMEM);

    // prep (3 kernels so gemm_logits_k is the 6th op incl. the 2 memcpys)
    norm_emb_k<<<2 * N_ROWS, 256>>>(speech, face, Sh, Fh);
    norm_mem_k<<<2 * S_ROWS, 256>>>(svm, fkm, Vh, Kh);
    transpose_half_k<<<dim3(C_DIM / 32, S_ROWS / 32), dim3(32, 8)>>>(svm, Vth);

    // merged logits GEMM: [2][8192,4096] = A[8192,256] x B[4096,256]^T
    gemm_logits_k<<<dim3(32, 64, 2), 256, GEMM_SMEM>>>(Sh, Vh, Fh, Kh, out + o_sal);

    // log-softmax (in place) + P = exp(logsm) fp16 over both matrices
    softmax_rows_k<<<2 * N_ROWS, 256>>>(out + o_sal, Ph);

    // merged recall GEMM (M=16384) with split-K=2 -> partials, then reduce
    gemm_recall_k<<<dim3(2, 128, 2), 256, GEMM_SMEM>>>(Ph, Vth, Part);
    reduce_recall_k<<<(2 * N_ROWS * C_DIM) / (256 * 4), 256>>>(Part, out + o_ser, out + o_fer);
}